// round 11
// baseline (speedup 1.0000x reference)
#include <cuda_runtime.h>
#include <cuda_fp16.h>
#include <mma.h>
#include <cstdint>

using namespace nvcuda;

#define M_DIM 8192
#define N_DIM 4096
#define K_DIM 4096
#define N_CODES (N_DIM * K_DIM / 8)   // 2,097,152
#define X_ELEMS (M_DIM * K_DIM)       // 33,554,432

__device__ __align__(16) __half g_W[(size_t)N_DIM * K_DIM];   // 32 MB
__device__ __align__(16) __half g_X[(size_t)M_DIM * K_DIM];   // 64 MB
__device__ int g_idx_is64;
__device__ int g_cb_mode;     // 0=fp16, 1=bf16, 2=fp32

// ======================= small PTX helpers =================================
__device__ __forceinline__ uint32_t smem_u32(const void* p) {
    uint32_t a;
    asm("{ .reg .u64 t; cvta.to.shared.u64 t, %1; cvt.u32.u64 %0, t; }"
        : "=r"(a) : "l"(p));
    return a;
}
__device__ __forceinline__ void cp16(uint32_t dst, const void* src) {
    asm volatile("cp.async.cg.shared.global [%0], [%1], 16;" :: "r"(dst), "l"(src));
}
#define CP_COMMIT() asm volatile("cp.async.commit_group;" ::: "memory")
#define CP_WAIT(n)  asm volatile("cp.async.wait_group %0;" :: "n"(n) : "memory")

// ======================= probe / dequant / convert =========================
__global__ void probe_kernel(const unsigned long long* __restrict__ idx64,
                             const unsigned short* __restrict__ cb_raw) {
    const int lane = threadIdx.x;
    unsigned long long hi = (lane < 16) ? (idx64[lane] >> 32) : 0ULL;
    int any_hi = __any_sync(0xFFFFFFFFu, hi != 0ULL);
    int big = 0, small = 0;
    for (int j = 0; j < 64; j++) {
        unsigned short u = cb_raw[lane * 64 + j];
        int expf = (u >> 10) & 0x1F;
        if (expf >= 21) big++;
        if (expf <= 13) small++;
    }
#pragma unroll
    for (int off = 16; off > 0; off >>= 1) {
        big   += __shfl_xor_sync(0xFFFFFFFFu, big, off);
        small += __shfl_xor_sync(0xFFFFFFFFu, small, off);
    }
    if (lane == 0) {
        g_idx_is64 = any_hi ? 0 : 1;
        g_cb_mode = (big > 0) ? 2 : ((small > 300) ? 0 : 1);
    }
}

__global__ void dequant_kernel(const void* __restrict__ indices,
                               const void* __restrict__ codebook) {
    int i = blockIdx.x * blockDim.x + threadIdx.x;
    if (i >= N_CODES) return;
    long long code;
    if (g_idx_is64) code = reinterpret_cast<const long long*>(indices)[i];
    else            code = reinterpret_cast<const int*>(indices)[i];
    code &= 255;
    const int mode = g_cb_mode;
    uint4 v;
    if (mode == 0) {
        v = __ldg(reinterpret_cast<const uint4*>(codebook) + code);
    } else if (mode == 2) {
        const float4* cb32 = reinterpret_cast<const float4*>(codebook);
        float4 a = __ldg(cb32 + 2 * code);
        float4 b = __ldg(cb32 + 2 * code + 1);
        __half2 h0 = __floats2half2_rn(a.x, a.y);
        __half2 h1 = __floats2half2_rn(a.z, a.w);
        __half2 h2 = __floats2half2_rn(b.x, b.y);
        __half2 h3 = __floats2half2_rn(b.z, b.w);
        v.x = *reinterpret_cast<unsigned*>(&h0);
        v.y = *reinterpret_cast<unsigned*>(&h1);
        v.z = *reinterpret_cast<unsigned*>(&h2);
        v.w = *reinterpret_cast<unsigned*>(&h3);
    } else {
        uint4 raw = __ldg(reinterpret_cast<const uint4*>(codebook) + code);
        unsigned* rw = reinterpret_cast<unsigned*>(&raw);
        unsigned* vw = reinterpret_cast<unsigned*>(&v);
#pragma unroll
        for (int w = 0; w < 4; w++) {
            float lo = __uint_as_float((rw[w] & 0xFFFFu) << 16);
            float hi = __uint_as_float(rw[w] & 0xFFFF0000u);
            __half2 h = __floats2half2_rn(lo, hi);
            vw[w] = *reinterpret_cast<unsigned*>(&h);
        }
    }
    reinterpret_cast<uint4*>(g_W)[i] = v;
}

__global__ void convert_kernel(const float* __restrict__ x) {
    int i = blockIdx.x * blockDim.x + threadIdx.x;
    if (i >= X_ELEMS / 8) return;
    const float4* in4 = reinterpret_cast<const float4*>(x);
    float4 a = in4[2 * i];
    float4 b = in4[2 * i + 1];
    __half2 h0 = __floats2half2_rn(a.x, a.y);
    __half2 h1 = __floats2half2_rn(a.z, a.w);
    __half2 h2 = __floats2half2_rn(b.x, b.y);
    __half2 h3 = __floats2half2_rn(b.z, b.w);
    uint4 o;
    o.x = *reinterpret_cast<unsigned*>(&h0);
    o.y = *reinterpret_cast<unsigned*>(&h1);
    o.z = *reinterpret_cast<unsigned*>(&h2);
    o.w = *reinterpret_cast<unsigned*>(&h3);
    reinterpret_cast<uint4*>(g_X)[i] = o;
}

// ======================= HMMA GEMM ========================================
// R9 config (best known): CTA 256x128, 512 thr = 16 warps (4Mx4N), warp 64x32,
// BK=64, 4-stage cp.async ring, CP_WAIT(2).
// NEW: per-warp kk-phase rotation to de-synchronize LDSM/HMMA bursts.
constexpr int BM = 256;
constexpr int BN = 128;
constexpr int BK = 64;
constexpr int STAGES = 4;
constexpr int LDSW = BK + 8;                          // 72 halves = 144 B row
constexpr int A_ST_BYTES = BM * LDSW * 2;             // 36864
constexpr int B_ST_BYTES = BN * LDSW * 2;             // 18432
constexpr int STAGE_BYTES = A_ST_BYTES + B_ST_BYTES;  // 55296
constexpr int SMEM_DYN = STAGES * STAGE_BYTES;        // 221184

__global__ __launch_bounds__(512, 1)
void gemm_hmma_kernel(float* __restrict__ out) {
    extern __shared__ __align__(16) char smem[];
    __half* sm = reinterpret_cast<__half*>(smem);
    const uint32_t smem_base = smem_u32(smem);

    const int tid = threadIdx.x;       // 0..511
    const int wid = tid >> 5;          // 0..15
    const size_t m0 = (size_t)blockIdx.y * BM;
    const size_t n0 = (size_t)blockIdx.x * BN;

    const int wm = wid >> 2;           // 0..3 -> 64-row slab
    const int wn = wid & 3;            // 0..3 -> 32-col slab
    const int krot = wid & 3;          // per-warp kk phase rotation

    // Loaders: A = 2048 chunks -> 4/thread ; B = 1024 chunks -> 2/thread
    const int a_row = tid >> 1;
    const int a_c0  = (tid & 1) * 4;
    const int b_row = tid >> 2;
    const int b_c0  = (tid & 3) * 2;

    const __half* Ag = g_X + (m0 + a_row) * (size_t)K_DIM + a_c0 * 8;
    const __half* Bg = g_W + (n0 + b_row) * (size_t)K_DIM + b_c0 * 8;
    const uint32_t a_dst = smem_base + a_row * (LDSW * 2) + a_c0 * 16;
    const uint32_t b_dst = smem_base + A_ST_BYTES + b_row * (LDSW * 2) + b_c0 * 16;

    auto load_stage = [&](int s) {
        const uint32_t soff = (uint32_t)(s & (STAGES - 1)) * STAGE_BYTES;
        const size_t ko = (size_t)s * BK;
#pragma unroll
        for (int c = 0; c < 4; c++) cp16(a_dst + soff + c * 16, Ag + ko + c * 8);
#pragma unroll
        for (int c = 0; c < 2; c++) cp16(b_dst + soff + c * 16, Bg + ko + c * 8);
        CP_COMMIT();
    };

    wmma::fragment<wmma::accumulator, 16, 16, 16, float> acc[4][2];
#pragma unroll
    for (int i = 0; i < 4; i++)
#pragma unroll
        for (int j = 0; j < 2; j++)
            wmma::fill_fragment(acc[i][j], 0.0f);

    load_stage(0);
    load_stage(1);
    load_stage(2);

    const int NT = K_DIM / BK;   // 64
    for (int s = 0; s < NT; s++) {
        if (s < NT - 2)       CP_WAIT(2);
        else if (s == NT - 2) CP_WAIT(1);
        else                  CP_WAIT(0);
        __syncthreads();

        if (s + 3 < NT) load_stage(s + 3);

        const __half* As = sm + (size_t)(s & (STAGES - 1)) * (STAGE_BYTES / 2);
        const __half* Bs = As + A_ST_BYTES / 2;

        // kk rotated per warp: de-phase LDSM vs HMMA bursts across warps.
#pragma unroll
        for (int kx = 0; kx < BK / 16; kx++) {
            const int kk = (kx + krot) & 3;
            wmma::fragment<wmma::matrix_a, 16, 16, 16, __half, wmma::row_major> af[4];
            wmma::fragment<wmma::matrix_b, 16, 16, 16, __half, wmma::col_major> bf[2];
#pragma unroll
            for (int j = 0; j < 2; j++)
                wmma::load_matrix_sync(bf[j], Bs + (wn * 32 + j * 16) * LDSW + kk * 16, LDSW);
#pragma unroll
            for (int i = 0; i < 4; i++) {
                const int im = (i + wm) & 3;   // rotate A-row order across M-slabs
                wmma::load_matrix_sync(af[im], As + (wm * 64 + im * 16) * LDSW + kk * 16, LDSW);
                wmma::mma_sync(acc[im][0], af[im], bf[0], acc[im][0]);
                wmma::mma_sync(acc[im][1], af[im], bf[1], acc[im][1]);
            }
        }
    }

    const size_t mb = m0 + wm * 64;
    const size_t nb = n0 + wn * 32;
#pragma unroll
    for (int i = 0; i < 4; i++)
#pragma unroll
        for (int j = 0; j < 2; j++)
            wmma::store_matrix_sync(out + (mb + i * 16) * N_DIM + (nb + j * 16),
                                    acc[i][j], N_DIM, wmma::mem_row_major);
}

// ======================= entry =============================================
extern "C" void kernel_launch(void* const* d_in, const int* in_sizes, int n_in,
                              void* d_out, int out_size) {
    const float* x        = nullptr;
    const void*  codebook = nullptr;
    const void*  indices  = nullptr;
    for (int i = 0; i < n_in; i++) {
        if      (in_sizes[i] == X_ELEMS)  x        = (const float*)d_in[i];
        else if (in_sizes[i] == 2048)     codebook = d_in[i];
        else if (in_sizes[i] == N_CODES)  indices  = d_in[i];
    }
    float* out = (float*)d_out;
    (void)out_size;

    cudaFuncSetAttribute(gemm_hmma_kernel,
                         cudaFuncAttributeMaxDynamicSharedMemorySize, SMEM_DYN);

    probe_kernel<<<1, 32>>>((const unsigned long long*)indices,
                            (const unsigned short*)codebook);
    dequant_kernel<<<(N_CODES + 255) / 256, 256>>>(indices, codebook);
    convert_kernel<<<(X_ELEMS / 8 + 255) / 256, 256>>>(x);

    dim3 grid(N_DIM / BN, M_DIM / BM);   // (32, 32)
    gemm_hmma_kernel<<<grid, 512, SMEM_DYN>>>(out);
}

// round 12
// speedup vs baseline: 5.9654x; 5.9654x over previous
#include <cuda_runtime.h>
#include <cuda_fp16.h>
#include <mma.h>
#include <cstdint>

using namespace nvcuda;

#define M_DIM 8192
#define N_DIM 4096
#define K_DIM 4096
#define N_CODES (N_DIM * K_DIM / 8)   // 2,097,152
#define X_ELEMS (M_DIM * K_DIM)       // 33,554,432

__device__ __align__(16) __half g_W[(size_t)N_DIM * K_DIM];   // 32 MB
__device__ __align__(16) __half g_X[(size_t)M_DIM * K_DIM];   // 64 MB
__device__ int g_idx_is64;
__device__ int g_cb_mode;     // 0=fp16, 1=bf16, 2=fp32

// ======================= small PTX helpers =================================
__device__ __forceinline__ uint32_t smem_u32(const void* p) {
    uint32_t a;
    asm("{ .reg .u64 t; cvta.to.shared.u64 t, %1; cvt.u32.u64 %0, t; }"
        : "=r"(a) : "l"(p));
    return a;
}
__device__ __forceinline__ void cp16(uint32_t dst, const void* src) {
    asm volatile("cp.async.cg.shared.global [%0], [%1], 16;" :: "r"(dst), "l"(src));
}
#define CP_COMMIT() asm volatile("cp.async.commit_group;" ::: "memory")
#define CP_WAIT(n)  asm volatile("cp.async.wait_group %0;" :: "n"(n) : "memory")

// ======================= probe / dequant / convert =========================
__global__ void probe_kernel(const unsigned long long* __restrict__ idx64,
                             const unsigned short* __restrict__ cb_raw) {
    const int lane = threadIdx.x;
    unsigned long long hi = (lane < 16) ? (idx64[lane] >> 32) : 0ULL;
    int any_hi = __any_sync(0xFFFFFFFFu, hi != 0ULL);
    int big = 0, small = 0;
    for (int j = 0; j < 64; j++) {
        unsigned short u = cb_raw[lane * 64 + j];
        int expf = (u >> 10) & 0x1F;
        if (expf >= 21) big++;
        if (expf <= 13) small++;
    }
#pragma unroll
    for (int off = 16; off > 0; off >>= 1) {
        big   += __shfl_xor_sync(0xFFFFFFFFu, big, off);
        small += __shfl_xor_sync(0xFFFFFFFFu, small, off);
    }
    if (lane == 0) {
        g_idx_is64 = any_hi ? 0 : 1;
        g_cb_mode = (big > 0) ? 2 : ((small > 300) ? 0 : 1);
    }
}

__global__ void dequant_kernel(const void* __restrict__ indices,
                               const void* __restrict__ codebook) {
    int i = blockIdx.x * blockDim.x + threadIdx.x;
    if (i >= N_CODES) return;
    long long code;
    if (g_idx_is64) code = reinterpret_cast<const long long*>(indices)[i];
    else            code = reinterpret_cast<const int*>(indices)[i];
    code &= 255;
    const int mode = g_cb_mode;
    uint4 v;
    if (mode == 0) {
        v = __ldg(reinterpret_cast<const uint4*>(codebook) + code);
    } else if (mode == 2) {
        const float4* cb32 = reinterpret_cast<const float4*>(codebook);
        float4 a = __ldg(cb32 + 2 * code);
        float4 b = __ldg(cb32 + 2 * code + 1);
        __half2 h0 = __floats2half2_rn(a.x, a.y);
        __half2 h1 = __floats2half2_rn(a.z, a.w);
        __half2 h2 = __floats2half2_rn(b.x, b.y);
        __half2 h3 = __floats2half2_rn(b.z, b.w);
        v.x = *reinterpret_cast<unsigned*>(&h0);
        v.y = *reinterpret_cast<unsigned*>(&h1);
        v.z = *reinterpret_cast<unsigned*>(&h2);
        v.w = *reinterpret_cast<unsigned*>(&h3);
    } else {
        uint4 raw = __ldg(reinterpret_cast<const uint4*>(codebook) + code);
        unsigned* rw = reinterpret_cast<unsigned*>(&raw);
        unsigned* vw = reinterpret_cast<unsigned*>(&v);
#pragma unroll
        for (int w = 0; w < 4; w++) {
            float lo = __uint_as_float((rw[w] & 0xFFFFu) << 16);
            float hi = __uint_as_float(rw[w] & 0xFFFF0000u);
            __half2 h = __floats2half2_rn(lo, hi);
            vw[w] = *reinterpret_cast<unsigned*>(&h);
        }
    }
    reinterpret_cast<uint4*>(g_W)[i] = v;
}

__global__ void convert_kernel(const float* __restrict__ x) {
    int i = blockIdx.x * blockDim.x + threadIdx.x;
    if (i >= X_ELEMS / 8) return;
    const float4* in4 = reinterpret_cast<const float4*>(x);
    float4 a = in4[2 * i];
    float4 b = in4[2 * i + 1];
    __half2 h0 = __floats2half2_rn(a.x, a.y);
    __half2 h1 = __floats2half2_rn(a.z, a.w);
    __half2 h2 = __floats2half2_rn(b.x, b.y);
    __half2 h3 = __floats2half2_rn(b.z, b.w);
    uint4 o;
    o.x = *reinterpret_cast<unsigned*>(&h0);
    o.y = *reinterpret_cast<unsigned*>(&h1);
    o.z = *reinterpret_cast<unsigned*>(&h2);
    o.w = *reinterpret_cast<unsigned*>(&h3);
    reinterpret_cast<uint4*>(g_X)[i] = o;
}

// ======================= HMMA GEMM ========================================
// R9 base: CTA 256x128, 512 thr = 16 warps (4Mx4N), warp 64x32, BK=64,
// 4-stage cp.async ring.  NEW: CP_WAIT(1) guarantees stage s+1 at iter s's
// barrier, so each warp prefetches next-iter kk=0 fragments at the END of
// compute(s) -> HMMAs issue immediately at the next barrier exit.
constexpr int BM = 256;
constexpr int BN = 128;
constexpr int BK = 64;
constexpr int STAGES = 4;
constexpr int LDSW = BK + 8;                          // 72 halves = 144 B row
constexpr int A_ST_BYTES = BM * LDSW * 2;             // 36864
constexpr int B_ST_BYTES = BN * LDSW * 2;             // 18432
constexpr int STAGE_BYTES = A_ST_BYTES + B_ST_BYTES;  // 55296
constexpr int SMEM_DYN = STAGES * STAGE_BYTES;        // 221184
constexpr int STAGE_HALVES = STAGE_BYTES / 2;
constexpr int A_ST_HALVES = A_ST_BYTES / 2;

__global__ __launch_bounds__(512, 1)
void gemm_hmma_kernel(float* __restrict__ out) {
    extern __shared__ __align__(16) char smem[];
    __half* sm = reinterpret_cast<__half*>(smem);
    const uint32_t smem_base = smem_u32(smem);

    const int tid = threadIdx.x;       // 0..511
    const int wid = tid >> 5;          // 0..15
    const size_t m0 = (size_t)blockIdx.y * BM;
    const size_t n0 = (size_t)blockIdx.x * BN;

    const int wm = wid >> 2;           // 0..3 -> 64-row slab
    const int wn = wid & 3;            // 0..3 -> 32-col slab

    // Loaders: A = 2048 chunks -> 4/thread ; B = 1024 chunks -> 2/thread
    const int a_row = tid >> 1;
    const int a_c0  = (tid & 1) * 4;
    const int b_row = tid >> 2;
    const int b_c0  = (tid & 3) * 2;

    const __half* Ag = g_X + (m0 + a_row) * (size_t)K_DIM + a_c0 * 8;
    const __half* Bg = g_W + (n0 + b_row) * (size_t)K_DIM + b_c0 * 8;
    const uint32_t a_dst = smem_base + a_row * (LDSW * 2) + a_c0 * 16;
    const uint32_t b_dst = smem_base + A_ST_BYTES + b_row * (LDSW * 2) + b_c0 * 16;

    auto load_stage = [&](int s) {
        const uint32_t soff = (uint32_t)(s & (STAGES - 1)) * STAGE_BYTES;
        const size_t ko = (size_t)s * BK;
#pragma unroll
        for (int c = 0; c < 4; c++) cp16(a_dst + soff + c * 16, Ag + ko + c * 8);
#pragma unroll
        for (int c = 0; c < 2; c++) cp16(b_dst + soff + c * 16, Bg + ko + c * 8);
        CP_COMMIT();
    };

    wmma::fragment<wmma::accumulator, 16, 16, 16, float> acc[4][2];
#pragma unroll
    for (int i = 0; i < 4; i++)
#pragma unroll
        for (int j = 0; j < 2; j++)
            wmma::fill_fragment(acc[i][j], 0.0f);

    // Held fragments for the NEXT iteration's kk=0 (prefetched).
    wmma::fragment<wmma::matrix_a, 16, 16, 16, __half, wmma::row_major> pf_a[4];
    wmma::fragment<wmma::matrix_b, 16, 16, 16, __half, wmma::col_major> pf_b[2];

    auto prefetch_kk0 = [&](int stage) {
        const __half* As = sm + (size_t)(stage & (STAGES - 1)) * STAGE_HALVES;
        const __half* Bs = As + A_ST_HALVES;
#pragma unroll
        for (int j = 0; j < 2; j++)
            wmma::load_matrix_sync(pf_b[j], Bs + (wn * 32 + j * 16) * LDSW, LDSW);
#pragma unroll
        for (int i = 0; i < 4; i++)
            wmma::load_matrix_sync(pf_a[i], As + (wm * 64 + i * 16) * LDSW, LDSW);
    };

    load_stage(0);
    load_stage(1);
    load_stage(2);

    CP_WAIT(1);           // groups 0,1 done (per-thread)
    __syncthreads();      // stages 0,1 visible to all
    prefetch_kk0(0);      // iter 0's kk=0 fragments into registers

    const int NT = K_DIM / BK;   // 64
    for (int s = 0; s < NT; s++) {
        // Guarantee stage s+1 complete (for the end-of-iter prefetch).
        if (s < NT - 1) CP_WAIT(1); else CP_WAIT(0);
        __syncthreads();   // stages <= s+1 visible; all reads of stage s-1 done

        if (s + 3 < NT) load_stage(s + 3);   // overwrite stage (s-1)%4: safe

        const __half* As = sm + (size_t)(s & (STAGES - 1)) * STAGE_HALVES;
        const __half* Bs = As + A_ST_HALVES;

        // kk = 0: HMMAs issue immediately from prefetched fragments.
#pragma unroll
        for (int i = 0; i < 4; i++) {
            wmma::mma_sync(acc[i][0], pf_a[i], pf_b[0], acc[i][0]);
            wmma::mma_sync(acc[i][1], pf_a[i], pf_b[1], acc[i][1]);
        }

        // kk = 1..3: load + mma (constant indices).
#pragma unroll
        for (int kk = 1; kk < BK / 16; kk++) {
            wmma::fragment<wmma::matrix_a, 16, 16, 16, __half, wmma::row_major> af[4];
            wmma::fragment<wmma::matrix_b, 16, 16, 16, __half, wmma::col_major> bf[2];
#pragma unroll
            for (int j = 0; j < 2; j++)
                wmma::load_matrix_sync(bf[j], Bs + (wn * 32 + j * 16) * LDSW + kk * 16, LDSW);
#pragma unroll
            for (int i = 0; i < 4; i++)
                wmma::load_matrix_sync(af[i], As + (wm * 64 + i * 16) * LDSW + kk * 16, LDSW);
#pragma unroll
            for (int i = 0; i < 4; i++) {
                wmma::mma_sync(acc[i][0], af[i], bf[0], acc[i][0]);
                wmma::mma_sync(acc[i][1], af[i], bf[1], acc[i][1]);
            }
        }

        // Prefetch next iteration's kk=0 fragments (stage s+1 is complete
        // and was made visible by THIS iteration's barrier).
        if (s + 1 < NT) prefetch_kk0(s + 1);
    }

    const size_t mb = m0 + wm * 64;
    const size_t nb = n0 + wn * 32;
#pragma unroll
    for (int i = 0; i < 4; i++)
#pragma unroll
        for (int j = 0; j < 2; j++)
            wmma::store_matrix_sync(out + (mb + i * 16) * N_DIM + (nb + j * 16),
                                    acc[i][j], N_DIM, wmma::mem_row_major);
}

// ======================= entry =============================================
extern "C" void kernel_launch(void* const* d_in, const int* in_sizes, int n_in,
                              void* d_out, int out_size) {
    const float* x        = nullptr;
    const void*  codebook = nullptr;
    const void*  indices  = nullptr;
    for (int i = 0; i < n_in; i++) {
        if      (in_sizes[i] == X_ELEMS)  x        = (const float*)d_in[i];
        else if (in_sizes[i] == 2048)     codebook = d_in[i];
        else if (in_sizes[i] == N_CODES)  indices  = d_in[i];
    }
    float* out = (float*)d_out;
    (void)out_size;

    cudaFuncSetAttribute(gemm_hmma_kernel,
                         cudaFuncAttributeMaxDynamicSharedMemorySize, SMEM_DYN);

    probe_kernel<<<1, 32>>>((const unsigned long long*)indices,
                            (const unsigned short*)codebook);
    dequant_kernel<<<(N_CODES + 255) / 256, 256>>>(indices, codebook);
    convert_kernel<<<(X_ELEMS / 8 + 255) / 256, 256>>>(x);

    dim3 grid(N_DIM / BN, M_DIM / BM);   // (32, 32)
    gemm_hmma_kernel<<<grid, 512, SMEM_DYN>>>(out);
}

// round 13
// speedup vs baseline: 6.0172x; 1.0087x over previous
#include <cuda_runtime.h>
#include <cuda_fp16.h>
#include <mma.h>
#include <cstdint>

using namespace nvcuda;

#define M_DIM 8192
#define N_DIM 4096
#define K_DIM 4096
#define N_CODES (N_DIM * K_DIM / 8)   // 2,097,152
#define X_ELEMS (M_DIM * K_DIM)       // 33,554,432

__device__ __align__(16) __half g_W[(size_t)N_DIM * K_DIM];   // 32 MB
__device__ __align__(16) __half g_X[(size_t)M_DIM * K_DIM];   // 64 MB
__device__ int g_idx_is64;
__device__ int g_cb_mode;     // 0=fp16, 1=bf16, 2=fp32

// ======================= small PTX helpers =================================
__device__ __forceinline__ uint32_t smem_u32(const void* p) {
    uint32_t a;
    asm("{ .reg .u64 t; cvta.to.shared.u64 t, %1; cvt.u32.u64 %0, t; }"
        : "=r"(a) : "l"(p));
    return a;
}
__device__ __forceinline__ void cp16(uint32_t dst, const void* src) {
    asm volatile("cp.async.cg.shared.global [%0], [%1], 16;" :: "r"(dst), "l"(src));
}
#define CP_COMMIT() asm volatile("cp.async.commit_group;" ::: "memory")
#define CP_WAIT(n)  asm volatile("cp.async.wait_group %0;" :: "n"(n) : "memory")

// ======================= probe / dequant / convert =========================
__global__ void probe_kernel(const unsigned long long* __restrict__ idx64,
                             const unsigned short* __restrict__ cb_raw) {
    const int lane = threadIdx.x;
    unsigned long long hi = (lane < 16) ? (idx64[lane] >> 32) : 0ULL;
    int any_hi = __any_sync(0xFFFFFFFFu, hi != 0ULL);
    int big = 0, small = 0;
    for (int j = 0; j < 64; j++) {
        unsigned short u = cb_raw[lane * 64 + j];
        int expf = (u >> 10) & 0x1F;
        if (expf >= 21) big++;
        if (expf <= 13) small++;
    }
#pragma unroll
    for (int off = 16; off > 0; off >>= 1) {
        big   += __shfl_xor_sync(0xFFFFFFFFu, big, off);
        small += __shfl_xor_sync(0xFFFFFFFFu, small, off);
    }
    if (lane == 0) {
        g_idx_is64 = any_hi ? 0 : 1;
        g_cb_mode = (big > 0) ? 2 : ((small > 300) ? 0 : 1);
    }
}

__global__ void dequant_kernel(const void* __restrict__ indices,
                               const void* __restrict__ codebook) {
    int i = blockIdx.x * blockDim.x + threadIdx.x;
    if (i >= N_CODES) return;
    long long code;
    if (g_idx_is64) code = reinterpret_cast<const long long*>(indices)[i];
    else            code = reinterpret_cast<const int*>(indices)[i];
    code &= 255;
    const int mode = g_cb_mode;
    uint4 v;
    if (mode == 0) {
        v = __ldg(reinterpret_cast<const uint4*>(codebook) + code);
    } else if (mode == 2) {
        const float4* cb32 = reinterpret_cast<const float4*>(codebook);
        float4 a = __ldg(cb32 + 2 * code);
        float4 b = __ldg(cb32 + 2 * code + 1);
        __half2 h0 = __floats2half2_rn(a.x, a.y);
        __half2 h1 = __floats2half2_rn(a.z, a.w);
        __half2 h2 = __floats2half2_rn(b.x, b.y);
        __half2 h3 = __floats2half2_rn(b.z, b.w);
        v.x = *reinterpret_cast<unsigned*>(&h0);
        v.y = *reinterpret_cast<unsigned*>(&h1);
        v.z = *reinterpret_cast<unsigned*>(&h2);
        v.w = *reinterpret_cast<unsigned*>(&h3);
    } else {
        uint4 raw = __ldg(reinterpret_cast<const uint4*>(codebook) + code);
        unsigned* rw = reinterpret_cast<unsigned*>(&raw);
        unsigned* vw = reinterpret_cast<unsigned*>(&v);
#pragma unroll
        for (int w = 0; w < 4; w++) {
            float lo = __uint_as_float((rw[w] & 0xFFFFu) << 16);
            float hi = __uint_as_float(rw[w] & 0xFFFF0000u);
            __half2 h = __floats2half2_rn(lo, hi);
            vw[w] = *reinterpret_cast<unsigned*>(&h);
        }
    }
    reinterpret_cast<uint4*>(g_W)[i] = v;
}

__global__ void convert_kernel(const float* __restrict__ x) {
    int i = blockIdx.x * blockDim.x + threadIdx.x;
    if (i >= X_ELEMS / 8) return;
    const float4* in4 = reinterpret_cast<const float4*>(x);
    float4 a = in4[2 * i];
    float4 b = in4[2 * i + 1];
    __half2 h0 = __floats2half2_rn(a.x, a.y);
    __half2 h1 = __floats2half2_rn(a.z, a.w);
    __half2 h2 = __floats2half2_rn(b.x, b.y);
    __half2 h3 = __floats2half2_rn(b.z, b.w);
    uint4 o;
    o.x = *reinterpret_cast<unsigned*>(&h0);
    o.y = *reinterpret_cast<unsigned*>(&h1);
    o.z = *reinterpret_cast<unsigned*>(&h2);
    o.w = *reinterpret_cast<unsigned*>(&h3);
    reinterpret_cast<uint4*>(g_X)[i] = o;
}

// ======================= HMMA GEMM ========================================
// R12 base + full even/odd register double-buffering of fragments:
// every kk's LDSM burst issues before the previous kk's HMMAs execute.
constexpr int BM = 256;
constexpr int BN = 128;
constexpr int BK = 64;
constexpr int STAGES = 4;
constexpr int LDSW = BK + 8;                          // 72 halves = 144 B row
constexpr int A_ST_BYTES = BM * LDSW * 2;             // 36864
constexpr int B_ST_BYTES = BN * LDSW * 2;             // 18432
constexpr int STAGE_BYTES = A_ST_BYTES + B_ST_BYTES;  // 55296
constexpr int SMEM_DYN = STAGES * STAGE_BYTES;        // 221184
constexpr int STAGE_HALVES = STAGE_BYTES / 2;
constexpr int A_ST_HALVES = A_ST_BYTES / 2;

__global__ __launch_bounds__(512, 1)
void gemm_hmma_kernel(float* __restrict__ out) {
    extern __shared__ __align__(16) char smem[];
    __half* sm = reinterpret_cast<__half*>(smem);
    const uint32_t smem_base = smem_u32(smem);

    const int tid = threadIdx.x;       // 0..511
    const int wid = tid >> 5;          // 0..15
    const size_t m0 = (size_t)blockIdx.y * BM;
    const size_t n0 = (size_t)blockIdx.x * BN;

    const int wm = wid >> 2;           // 0..3 -> 64-row slab
    const int wn = wid & 3;            // 0..3 -> 32-col slab

    // Loaders: A = 2048 chunks -> 4/thread ; B = 1024 chunks -> 2/thread
    const int a_row = tid >> 1;
    const int a_c0  = (tid & 1) * 4;
    const int b_row = tid >> 2;
    const int b_c0  = (tid & 3) * 2;

    const __half* Ag = g_X + (m0 + a_row) * (size_t)K_DIM + a_c0 * 8;
    const __half* Bg = g_W + (n0 + b_row) * (size_t)K_DIM + b_c0 * 8;
    const uint32_t a_dst = smem_base + a_row * (LDSW * 2) + a_c0 * 16;
    const uint32_t b_dst = smem_base + A_ST_BYTES + b_row * (LDSW * 2) + b_c0 * 16;

    auto load_stage = [&](int s) {
        const uint32_t soff = (uint32_t)(s & (STAGES - 1)) * STAGE_BYTES;
        const size_t ko = (size_t)s * BK;
#pragma unroll
        for (int c = 0; c < 4; c++) cp16(a_dst + soff + c * 16, Ag + ko + c * 8);
#pragma unroll
        for (int c = 0; c < 2; c++) cp16(b_dst + soff + c * 16, Bg + ko + c * 8);
        CP_COMMIT();
    };

    wmma::fragment<wmma::accumulator, 16, 16, 16, float> acc[4][2];
#pragma unroll
    for (int i = 0; i < 4; i++)
#pragma unroll
        for (int j = 0; j < 2; j++)
            wmma::fill_fragment(acc[i][j], 0.0f);

    // Two fragment sets (even/odd). Statically indexed only.
    wmma::fragment<wmma::matrix_a, 16, 16, 16, __half, wmma::row_major> aA[4], aB[4];
    wmma::fragment<wmma::matrix_b, 16, 16, 16, __half, wmma::col_major> bA[2], bB[2];

    // Per-warp smem tile bases for the current stage.
    auto stage_A = [&](int s) { return sm + (size_t)(s & (STAGES - 1)) * STAGE_HALVES
                                          + (wm * 64) * LDSW; };
    auto stage_B = [&](int s) { return sm + (size_t)(s & (STAGES - 1)) * STAGE_HALVES
                                          + A_ST_HALVES + (wn * 32) * LDSW; };

    auto load_setA = [&](const __half* Aw, const __half* Bw, int kk) {
#pragma unroll
        for (int j = 0; j < 2; j++)
            wmma::load_matrix_sync(bA[j], Bw + j * 16 * LDSW + kk * 16, LDSW);
#pragma unroll
        for (int i = 0; i < 4; i++)
            wmma::load_matrix_sync(aA[i], Aw + i * 16 * LDSW + kk * 16, LDSW);
    };
    auto load_setB = [&](const __half* Aw, const __half* Bw, int kk) {
#pragma unroll
        for (int j = 0; j < 2; j++)
            wmma::load_matrix_sync(bB[j], Bw + j * 16 * LDSW + kk * 16, LDSW);
#pragma unroll
        for (int i = 0; i < 4; i++)
            wmma::load_matrix_sync(aB[i], Aw + i * 16 * LDSW + kk * 16, LDSW);
    };
    auto mma_setA = [&]() {
#pragma unroll
        for (int i = 0; i < 4; i++) {
            wmma::mma_sync(acc[i][0], aA[i], bA[0], acc[i][0]);
            wmma::mma_sync(acc[i][1], aA[i], bA[1], acc[i][1]);
        }
    };
    auto mma_setB = [&]() {
#pragma unroll
        for (int i = 0; i < 4; i++) {
            wmma::mma_sync(acc[i][0], aB[i], bB[0], acc[i][0]);
            wmma::mma_sync(acc[i][1], aB[i], bB[1], acc[i][1]);
        }
    };

    load_stage(0);
    load_stage(1);
    load_stage(2);

    CP_WAIT(1);           // stages 0,1 complete (per-thread)
    __syncthreads();      // ... and visible to all
    load_setA(stage_A(0), stage_B(0), 0);   // iter 0 kk0 into set A

    const int NT = K_DIM / BK;   // 64
    for (int s = 0; s < NT; s++) {
        if (s < NT - 1) CP_WAIT(1); else CP_WAIT(0);   // stage s+1 complete
        __syncthreads();   // visible; all reads of stage s-1 finished

        if (s + 3 < NT) load_stage(s + 3);

        const __half* Aw = stage_A(s);
        const __half* Bw = stage_B(s);

        // Even/odd pipeline: loads for kk+1 issue before mma of kk.
        load_setB(Aw, Bw, 1);  mma_setA();        // kk0 from prefetch
        load_setA(Aw, Bw, 2);  mma_setB();        // kk1
        load_setB(Aw, Bw, 3);  mma_setA();        // kk2
        if (s + 1 < NT)
            load_setA(stage_A(s + 1), stage_B(s + 1), 0);  // next iter kk0
        mma_setB();                                // kk3
    }

    const size_t mb = m0 + wm * 64;
    const size_t nb = n0 + wn * 32;
#pragma unroll
    for (int i = 0; i < 4; i++)
#pragma unroll
        for (int j = 0; j < 2; j++)
            wmma::store_matrix_sync(out + (mb + i * 16) * N_DIM + (nb + j * 16),
                                    acc[i][j], N_DIM, wmma::mem_row_major);
}

// ======================= entry =============================================
extern "C" void kernel_launch(void* const* d_in, const int* in_sizes, int n_in,
                              void* d_out, int out_size) {
    const float* x        = nullptr;
    const void*  codebook = nullptr;
    const void*  indices  = nullptr;
    for (int i = 0; i < n_in; i++) {
        if      (in_sizes[i] == X_ELEMS)  x        = (const float*)d_in[i];
        else if (in_sizes[i] == 2048)     codebook = d_in[i];
        else if (in_sizes[i] == N_CODES)  indices  = d_in[i];
    }
    float* out = (float*)d_out;
    (void)out_size;

    cudaFuncSetAttribute(gemm_hmma_kernel,
                         cudaFuncAttributeMaxDynamicSharedMemorySize, SMEM_DYN);

    probe_kernel<<<1, 32>>>((const unsigned long long*)indices,
                            (const unsigned short*)codebook);
    dequant_kernel<<<(N_CODES + 255) / 256, 256>>>(indices, codebook);
    convert_kernel<<<(X_ELEMS / 8 + 255) / 256, 256>>>(x);

    dim3 grid(N_DIM / BN, M_DIM / BM);   // (32, 32)
    gemm_hmma_kernel<<<grid, 512, SMEM_DYN>>>(out);
}